// round 2
// baseline (speedup 1.0000x reference)
#include <cuda_runtime.h>
#include <cstdint>

#define N_NODES 100000
#define N_EDGES 1250000
#define D 64

// Scratch: transformed node features g = h @ W^T  (25.6 MB)
__device__ float g_feat[(size_t)N_NODES * D];

// ---------------------------------------------------------------------------
// Kernel 1: g = h @ W^T
// Persistent blocks so W is loaded into smem once per block.
// ---------------------------------------------------------------------------
__global__ void transform_kernel(const float* __restrict__ h,
                                 const float* __restrict__ W) {
    __shared__ float Wt[D * D];      // Wt[k*D + o] = W[o*D + k]
    __shared__ float hrow[4 * D];    // 4 rows per iteration (256 threads)

    for (int i = threadIdx.x; i < D * D; i += blockDim.x) {
        int o = i / D, k = i % D;
        Wt[k * D + o] = W[i];
    }
    __syncthreads();

    const int rpb  = blockDim.x / D;        // 4 rows per block-iter
    const int r_in = threadIdx.x / D;
    const int o    = threadIdx.x & (D - 1);

    for (int base = blockIdx.x * rpb; base < N_NODES; base += gridDim.x * rpb) {
        int row = base + r_in;
        if (row < N_NODES) hrow[r_in * D + o] = h[(size_t)row * D + o];
        __syncthreads();
        if (row < N_NODES) {
            float acc = 0.f;
#pragma unroll
            for (int k = 0; k < D; k++)
                acc = fmaf(Wt[k * D + o], hrow[r_in * D + k], acc);
            g_feat[(size_t)row * D + o] = acc;
        }
        __syncthreads();   // protect hrow before next iteration overwrites
    }
}

// ---------------------------------------------------------------------------
// Kernel 2: out[n][o] = b[o]  (bias init; nodes with no in-edges get just b)
// ---------------------------------------------------------------------------
__global__ void init_out_kernel(float* __restrict__ out,
                                const float* __restrict__ b) {
    size_t i = (size_t)blockIdx.x * blockDim.x + threadIdx.x;
    if (i < (size_t)N_NODES * D) out[i] = __ldg(&b[i & (D - 1)]);
}

// ---------------------------------------------------------------------------
// Kernel 3: per-edge scatter. 16 threads per edge, one float4 each.
// out[dst] += g[src] * e   via red.global.add.v4.f32 (sm_90+ vector RED).
// g (25.6 MB) and out (25.6 MB) are both L2-resident.
// NOTE: src/dst arrive as int32 (JAX x64-disabled canonicalizes int64->int32).
// ---------------------------------------------------------------------------
__global__ void scatter_kernel(const float* __restrict__ e,
                               const int* __restrict__ src,
                               const int* __restrict__ dst,
                               float* __restrict__ out) {
    long long t = (long long)blockIdx.x * blockDim.x + threadIdx.x;
    int edge = (int)(t >> 4);
    if (edge >= N_EDGES) return;
    int quad = ((int)t & 15) * 4;

    int   s  = src[edge];
    int   d  = dst[edge];
    float ev = e[edge];

    const float4 gv =
        *reinterpret_cast<const float4*>(&g_feat[(size_t)s * D + quad]);

    float4 m = make_float4(gv.x * ev, gv.y * ev, gv.z * ev, gv.w * ev);

    float* p = &out[(size_t)d * D + quad];
    asm volatile("red.global.add.v4.f32 [%0], {%1, %2, %3, %4};"
                 :: "l"(p), "f"(m.x), "f"(m.y), "f"(m.z), "f"(m.w)
                 : "memory");
}

// ---------------------------------------------------------------------------
// Launch: h, e, src, dst, W, b  ->  out [N_NODES, D] float32
// ---------------------------------------------------------------------------
extern "C" void kernel_launch(void* const* d_in, const int* in_sizes, int n_in,
                              void* d_out, int out_size) {
    const float* h   = (const float*)d_in[0];
    const float* e   = (const float*)d_in[1];
    const int*   src = (const int*)d_in[2];
    const int*   dst = (const int*)d_in[3];
    const float* W   = (const float*)d_in[4];
    const float* b   = (const float*)d_in[5];
    float*       out = (float*)d_out;

    // 1) g = h @ W^T  (persistent blocks; W loaded to smem once per block)
    transform_kernel<<<1480, 256>>>(h, W);

    // 2) out = broadcast(b)
    {
        size_t total = (size_t)N_NODES * D;
        int blocks = (int)((total + 255) / 256);
        init_out_kernel<<<blocks, 256>>>(out, b);
    }

    // 3) out[dst] += g[src] * e   (16 threads/edge, vector RED)
    {
        long long total = (long long)N_EDGES * 16;
        int blocks = (int)((total + 255) / 256);
        scatter_kernel<<<blocks, 256>>>(e, src, dst, out);
    }
}

// round 4
// speedup vs baseline: 1.0194x; 1.0194x over previous
#include <cuda_runtime.h>
#include <cstdint>

#define N_NODES 100000
#define N_EDGES 1250000
#define D 64
#define ROWS_PER_BLOCK 32
#define TPB 256
#define H_STRIDE 68   // padded row stride in floats (17 float4) -> conflict-free

// Scratch: transformed node features g = h @ W^T  (25.6 MB)
__device__ float g_feat[(size_t)N_NODES * D];

// ---------------------------------------------------------------------------
// Kernel 1: g = h @ W^T  — register-tiled.
// Block: 256 threads, 32 rows. Warp covers 8 rows x 32 output cols.
// Thread: 8 outputs (o_base..o_base+7) of one row, acc in registers.
// Per k-step per warp: 8 FFMA-instr vs 3 conflict-free LDS wavefronts.
// ---------------------------------------------------------------------------
__global__ __launch_bounds__(TPB) void transform_kernel(
        const float* __restrict__ h, const float* __restrict__ W) {
    __shared__ float Wt[D * D];                    // Wt[k*64+o] = W[o*64+k]
    __shared__ float h_s[ROWS_PER_BLOCK * H_STRIDE];

    const int tid = threadIdx.x;

    // Load + transpose W (one time, 16 KB)
    for (int i = tid; i < D * D; i += TPB) {
        int o = i >> 6, k = i & 63;
        Wt[k * D + o] = W[i];
    }

    // Load 32 rows of h as float4 (contiguous 8 KB from global)
    const int row_base = blockIdx.x * ROWS_PER_BLOCK;
    const float4* hg = reinterpret_cast<const float4*>(h + (size_t)row_base * D);
#pragma unroll
    for (int i = 0; i < 2; i++) {
        int gi  = tid + i * TPB;          // [0, 512)
        int row = gi >> 4;                // 16 float4 per row
        int c4  = gi & 15;
        reinterpret_cast<float4*>(h_s)[row * (H_STRIDE / 4) + c4] = hg[gi];
    }
    __syncthreads();

    // Thread mapping
    const int warp = tid >> 5;
    const int lane = tid & 31;
    const int rowg = warp >> 1;                  // 0..3
    const int half = warp & 1;                   // which 32-col half of output
    const int row_local = rowg * 8 + (lane >> 2);
    const int o_base = half * 32 + (lane & 3) * 8;

    const float* hrow = &h_s[row_local * H_STRIDE];

    float4 a0 = make_float4(0.f, 0.f, 0.f, 0.f);
    float4 a1 = make_float4(0.f, 0.f, 0.f, 0.f);

#pragma unroll 16
    for (int k = 0; k < D; k++) {
        float hv = hrow[k];
        const float4 w0 = *reinterpret_cast<const float4*>(&Wt[k * D + o_base]);
        const float4 w1 = *reinterpret_cast<const float4*>(&Wt[k * D + o_base + 4]);
        a0.x = fmaf(hv, w0.x, a0.x);
        a0.y = fmaf(hv, w0.y, a0.y);
        a0.z = fmaf(hv, w0.z, a0.z);
        a0.w = fmaf(hv, w0.w, a0.w);
        a1.x = fmaf(hv, w1.x, a1.x);
        a1.y = fmaf(hv, w1.y, a1.y);
        a1.z = fmaf(hv, w1.z, a1.z);
        a1.w = fmaf(hv, w1.w, a1.w);
    }

    float* gout = &g_feat[(size_t)(row_base + row_local) * D + o_base];
    *reinterpret_cast<float4*>(gout)     = a0;
    *reinterpret_cast<float4*>(gout + 4) = a1;
}

// ---------------------------------------------------------------------------
// Kernel 2: out[n][o] = b[o]
// ---------------------------------------------------------------------------
__global__ void init_out_kernel(float* __restrict__ out,
                                const float* __restrict__ b) {
    size_t i = (size_t)blockIdx.x * blockDim.x + threadIdx.x;
    if (i < (size_t)N_NODES * D) out[i] = __ldg(&b[i & (D - 1)]);
}

// ---------------------------------------------------------------------------
// Kernel 3: per-edge scatter. 16 threads per edge, one float4 each.
// out[dst] += g[src] * e   via red.global.add.v4.f32.
// ---------------------------------------------------------------------------
__global__ void scatter_kernel(const float* __restrict__ e,
                               const int* __restrict__ src,
                               const int* __restrict__ dst,
                               float* __restrict__ out) {
    long long t = (long long)blockIdx.x * blockDim.x + threadIdx.x;
    int edge = (int)(t >> 4);
    if (edge >= N_EDGES) return;
    int quad = ((int)t & 15) * 4;

    int   s  = src[edge];
    int   d  = dst[edge];
    float ev = e[edge];

    const float4 gv =
        *reinterpret_cast<const float4*>(&g_feat[(size_t)s * D + quad]);

    float4 m = make_float4(gv.x * ev, gv.y * ev, gv.z * ev, gv.w * ev);

    float* p = &out[(size_t)d * D + quad];
    asm volatile("red.global.add.v4.f32 [%0], {%1, %2, %3, %4};"
                 :: "l"(p), "f"(m.x), "f"(m.y), "f"(m.z), "f"(m.w)
                 : "memory");
}

// ---------------------------------------------------------------------------
extern "C" void kernel_launch(void* const* d_in, const int* in_sizes, int n_in,
                              void* d_out, int out_size) {
    const float* h   = (const float*)d_in[0];
    const float* e   = (const float*)d_in[1];
    const int*   src = (const int*)d_in[2];
    const int*   dst = (const int*)d_in[3];
    const float* W   = (const float*)d_in[4];
    const float* b   = (const float*)d_in[5];
    float*       out = (float*)d_out;

    // 1) g = h @ W^T  (register-tiled, 3125 blocks x 32 rows)
    transform_kernel<<<N_NODES / ROWS_PER_BLOCK, TPB>>>(h, W);

    // 2) out = broadcast(b)
    {
        size_t total = (size_t)N_NODES * D;
        int blocks = (int)((total + 255) / 256);
        init_out_kernel<<<blocks, 256>>>(out, b);
    }

    // 3) out[dst] += g[src] * e
    {
        long long total = (long long)N_EDGES * 16;
        int blocks = (int)((total + 255) / 256);
        scatter_kernel<<<blocks, 256>>>(e, src, dst, out);
    }
}

// round 9
// speedup vs baseline: 1.3998x; 1.3732x over previous
#include <cuda_runtime.h>
#include <cstdint>

#define N_NODES 100000
#define N_EDGES 1250000
#define D 64

// transform tiling
#define T_TPB 128
#define BLOCK_ROWS 256      // 32 row-groups x 8 rows
#define KT 16               // k-tile held in shared
#define HS 380              // hT row stride: rp = row + (row>>3)*4, max 379; mult of 4

// Scratch: transformed node features g = h @ W^T  (25.6 MB)
__device__ float g_feat[(size_t)N_NODES * D];

// ---------------------------------------------------------------------------
// Kernel 1: g = h @ W^T
// Thread tile: 8 rows x 16 cols, accumulators packed as f32x2 (fma.rn.f32x2).
// h staged transposed + INJECTIVE skew rp = row + (row>>3)*4:
//   row-group q of warp w reads float offset 96w + 12q (mod 32 all distinct,
//   8 disjoint 4-float spans -> conflict-free LDS.128).
// W staged with c4 bit-swap (conflict-free LDS.128 across col-groups).
// ---------------------------------------------------------------------------
__global__ __launch_bounds__(T_TPB) void transform_kernel(
        const float* __restrict__ h, const float* __restrict__ W) {
    __shared__ float Wt[D * D];          // phys layout: [k][bitswap(c4)][elem]
    __shared__ float hT[KT * HS];        // [k_local][skewed row]

    const int tid = threadIdx.x;

    // Load W transposed with bit-swapped c4:
    // logical c4 (cols 4*c4..+3 of W^T row k) stored at phys ((c4&3)<<2)|(c4>>2)
    for (int i = tid; i < D * D; i += T_TPB) {
        int o = i >> 6, k = i & 63;      // W[o][k]
        int c4 = o >> 2, el = o & 3;
        int phys = ((c4 & 3) << 2) | (c4 >> 2);
        Wt[k * 64 + phys * 4 + el] = W[i];
    }

    const int cg  = tid & 3;             // col group: cols cg*16..+15
    const int rg  = tid >> 2;            // row group 0..31: rows rg*8..+7
    const int row0 = blockIdx.x * BLOCK_ROWS + rg * 8;
    const int rbp  = rg * 12;            // skewed base row index in hT

    unsigned long long acc[8][8];
#pragma unroll
    for (int i = 0; i < 8; i++)
#pragma unroll
        for (int p = 0; p < 8; p++) acc[i][p] = 0ULL;

    const int base_row = blockIdx.x * BLOCK_ROWS;

    for (int kp = 0; kp < D / KT; kp++) {
        __syncthreads();
        // Stage h[*, kp*KT .. +KT-1] for 256 rows, transposed + skewed.
#pragma unroll
        for (int it = 0; it < 8; it++) {
            int gi  = tid + it * T_TPB;          // 0..1023
            int row = gi & 255;
            int c4  = gi >> 8;                   // 0..3
            int grow = base_row + row;
            if (grow > N_NODES - 1) grow = N_NODES - 1;
            float4 hv = *reinterpret_cast<const float4*>(
                &h[(size_t)grow * D + kp * KT + c4 * 4]);
            int rp = row + (row >> 3) * 4;       // injective skew
            hT[(c4 * 4 + 0) * HS + rp] = hv.x;
            hT[(c4 * 4 + 1) * HS + rp] = hv.y;
            hT[(c4 * 4 + 2) * HS + rp] = hv.z;
            hT[(c4 * 4 + 3) * HS + rp] = hv.w;
        }
        __syncthreads();

#pragma unroll 4
        for (int kl = 0; kl < KT; kl++) {
            const int k = kp * KT + kl;
            // h: 8 row values (2 conflict-free LDS.128)
            float4 ha = *reinterpret_cast<const float4*>(&hT[kl * HS + rbp]);
            float4 hb = *reinterpret_cast<const float4*>(&hT[kl * HS + rbp + 4]);
            unsigned long long h2[8];
            asm("mov.b64 %0, {%1, %1};" : "=l"(h2[0]) : "r"(__float_as_uint(ha.x)));
            asm("mov.b64 %0, {%1, %1};" : "=l"(h2[1]) : "r"(__float_as_uint(ha.y)));
            asm("mov.b64 %0, {%1, %1};" : "=l"(h2[2]) : "r"(__float_as_uint(ha.z)));
            asm("mov.b64 %0, {%1, %1};" : "=l"(h2[3]) : "r"(__float_as_uint(ha.w)));
            asm("mov.b64 %0, {%1, %1};" : "=l"(h2[4]) : "r"(__float_as_uint(hb.x)));
            asm("mov.b64 %0, {%1, %1};" : "=l"(h2[5]) : "r"(__float_as_uint(hb.y)));
            asm("mov.b64 %0, {%1, %1};" : "=l"(h2[6]) : "r"(__float_as_uint(hb.z)));
            asm("mov.b64 %0, {%1, %1};" : "=l"(h2[7]) : "r"(__float_as_uint(hb.w)));

#pragma unroll
            for (int j = 0; j < 4; j++) {
                // logical c4 = cg*4+j at phys (j<<2)|cg -> 16B-spaced across cg
                ulonglong2 wj = *reinterpret_cast<const ulonglong2*>(
                    &Wt[k * 64 + (((j << 2) | cg) << 2)]);
#pragma unroll
                for (int i = 0; i < 8; i++) {
                    asm("fma.rn.f32x2 %0, %1, %2, %0;"
                        : "+l"(acc[i][2 * j]) : "l"(h2[i]), "l"(wj.x));
                    asm("fma.rn.f32x2 %0, %1, %2, %0;"
                        : "+l"(acc[i][2 * j + 1]) : "l"(h2[i]), "l"(wj.y));
                }
            }
        }
    }

    // Store 8 rows x 16 cols (4 x 16B per row)
#pragma unroll
    for (int i = 0; i < 8; i++) {
        int row = row0 + i;
        if (row < N_NODES) {
            float* gp = &g_feat[(size_t)row * D + cg * 16];
            reinterpret_cast<ulonglong2*>(gp)[0] = make_ulonglong2(acc[i][0], acc[i][1]);
            reinterpret_cast<ulonglong2*>(gp)[1] = make_ulonglong2(acc[i][2], acc[i][3]);
            reinterpret_cast<ulonglong2*>(gp)[2] = make_ulonglong2(acc[i][4], acc[i][5]);
            reinterpret_cast<ulonglong2*>(gp)[3] = make_ulonglong2(acc[i][6], acc[i][7]);
        }
    }
}

// ---------------------------------------------------------------------------
// Kernel 2: out[n][o] = b[o]
// ---------------------------------------------------------------------------
__global__ void init_out_kernel(float* __restrict__ out,
                                const float* __restrict__ b) {
    size_t i = (size_t)blockIdx.x * blockDim.x + threadIdx.x;
    if (i < (size_t)N_NODES * D) out[i] = __ldg(&b[i & (D - 1)]);
}

// ---------------------------------------------------------------------------
// Kernel 3: per-edge scatter. 16 threads per edge, one float4 each.
// out[dst] += g[src] * e   via red.global.add.v4.f32.
// ---------------------------------------------------------------------------
__global__ void scatter_kernel(const float* __restrict__ e,
                               const int* __restrict__ src,
                               const int* __restrict__ dst,
                               float* __restrict__ out) {
    long long t = (long long)blockIdx.x * blockDim.x + threadIdx.x;
    int edge = (int)(t >> 4);
    if (edge >= N_EDGES) return;
    int quad = ((int)t & 15) * 4;

    int   s  = src[edge];
    int   d  = dst[edge];
    float ev = e[edge];

    const float4 gv =
        *reinterpret_cast<const float4*>(&g_feat[(size_t)s * D + quad]);

    float4 m = make_float4(gv.x * ev, gv.y * ev, gv.z * ev, gv.w * ev);

    float* p = &out[(size_t)d * D + quad];
    asm volatile("red.global.add.v4.f32 [%0], {%1, %2, %3, %4};"
                 :: "l"(p), "f"(m.x), "f"(m.y), "f"(m.z), "f"(m.w)
                 : "memory");
}

// ---------------------------------------------------------------------------
extern "C" void kernel_launch(void* const* d_in, const int* in_sizes, int n_in,
                              void* d_out, int out_size) {
    const float* h   = (const float*)d_in[0];
    const float* e   = (const float*)d_in[1];
    const int*   src = (const int*)d_in[2];
    const int*   dst = (const int*)d_in[3];
    const float* W   = (const float*)d_in[4];
    const float* b   = (const float*)d_in[5];
    float*       out = (float*)d_out;

    // 1) g = h @ W^T
    int tblocks = (N_NODES + BLOCK_ROWS - 1) / BLOCK_ROWS;   // 391
    transform_kernel<<<tblocks, T_TPB>>>(h, W);

    // 2) out = broadcast(b)
    {
        size_t total = (size_t)N_NODES * D;
        int blocks = (int)((total + 255) / 256);
        init_out_kernel<<<blocks, 256>>>(out, b);
    }

    // 3) out[dst] += g[src] * e
    {
        long long total = (long long)N_EDGES * 16;
        int blocks = (int)((total + 255) / 256);
        scatter_kernel<<<blocks, 256>>>(e, src, dst, out);
    }
}

// round 10
// speedup vs baseline: 1.5855x; 1.1327x over previous
#include <cuda_runtime.h>
#include <cstdint>

#define N_NODES 100000
#define N_EDGES 1250000
#define D 64

// transform tiling
#define T_TPB 256
#define BLOCK_ROWS 256      // 32 row-groups x 8 rows
#define KT 16               // k-tile held in shared
#define HS 380              // hT row stride: rp = row + (row>>3)*4 (injective)

// Scratch: transformed node features g = h @ W^T  (25.6 MB)
__device__ float g_feat[(size_t)N_NODES * D];

// ---------------------------------------------------------------------------
// Kernel 1: g = h @ W^T, and out = broadcast(b) (fused bias init).
// Thread tile: 8 rows x 8 cols, acc packed f32x2. 256 thr: 32 row-groups x 8
// col-groups. Warp covers 4 row-groups x 8 col-groups.
//   h LDS: rg = w*4+q -> float offset 12*rg; 4 distinct 16B spans, 8-lane
//   broadcast each -> conflict-free.
//   W LDS: 16B-unit permutation p=((u&1)<<3)|(u>>1); load1 at unit cg,
//   load2 at unit 8+cg -> each spans all 32 banks exactly once.
// ---------------------------------------------------------------------------
__global__ __launch_bounds__(T_TPB, 2) void transform_kernel(
        const float* __restrict__ h, const float* __restrict__ W,
        const float* __restrict__ b, float* __restrict__ out) {
    __shared__ float Wt[D * D];          // [k][perm unit p][elem]
    __shared__ float hT[KT * HS];        // [k_local][skewed row]

    const int tid = threadIdx.x;

    // Load W transposed with 16B-unit permutation.
    for (int i = tid; i < D * D; i += T_TPB) {
        int o = i >> 6, k = i & 63;      // W[o][k] -> col o of W^T row k
        int u = o >> 2, el = o & 3;
        int p = ((u & 1) << 3) | (u >> 1);
        Wt[k * 64 + p * 4 + el] = W[i];
    }

    const int warp = tid >> 5;
    const int lane = tid & 31;
    const int cg   = lane & 7;               // col group: cols cg*8..+7
    const int rg   = warp * 4 + (lane >> 3); // row group 0..31: rows rg*8..+7
    const int row0 = blockIdx.x * BLOCK_ROWS + rg * 8;
    const int rbp  = rg * 12;                // skewed base row in hT

    // Fused bias init: this block owns rows row0-block..+255 of out.
    {
        float4 b0 = __ldg(reinterpret_cast<const float4*>(&b[cg * 8]));
        float4 b1 = __ldg(reinterpret_cast<const float4*>(&b[cg * 8 + 4]));
#pragma unroll
        for (int i = 0; i < 8; i++) {
            int row = row0 + i;
            if (row < N_NODES) {
                float* op = &out[(size_t)row * D + cg * 8];
                *reinterpret_cast<float4*>(op)     = b0;
                *reinterpret_cast<float4*>(op + 4) = b1;
            }
        }
    }

    unsigned long long acc[8][4];
#pragma unroll
    for (int i = 0; i < 8; i++)
#pragma unroll
        for (int p = 0; p < 4; p++) acc[i][p] = 0ULL;

    const int base_row = blockIdx.x * BLOCK_ROWS;

    for (int kp = 0; kp < D / KT; kp++) {
        __syncthreads();
        // Stage h[*, kp*KT..+15] for 256 rows, transposed + injective skew.
#pragma unroll
        for (int it = 0; it < 4; it++) {
            int gi  = tid + it * T_TPB;          // 0..1023
            int row = gi & 255;
            int c4  = gi >> 8;                   // 0..3
            int grow = base_row + row;
            if (grow > N_NODES - 1) grow = N_NODES - 1;
            float4 hv = *reinterpret_cast<const float4*>(
                &h[(size_t)grow * D + kp * KT + c4 * 4]);
            int rp = row + (row >> 3) * 4;
            hT[(c4 * 4 + 0) * HS + rp] = hv.x;
            hT[(c4 * 4 + 1) * HS + rp] = hv.y;
            hT[(c4 * 4 + 2) * HS + rp] = hv.z;
            hT[(c4 * 4 + 3) * HS + rp] = hv.w;
        }
        __syncthreads();

#pragma unroll 4
        for (int kl = 0; kl < KT; kl++) {
            const int k = kp * KT + kl;
            float4 ha = *reinterpret_cast<const float4*>(&hT[kl * HS + rbp]);
            float4 hb = *reinterpret_cast<const float4*>(&hT[kl * HS + rbp + 4]);
            unsigned long long h2[8];
            asm("mov.b64 %0, {%1, %1};" : "=l"(h2[0]) : "r"(__float_as_uint(ha.x)));
            asm("mov.b64 %0, {%1, %1};" : "=l"(h2[1]) : "r"(__float_as_uint(ha.y)));
            asm("mov.b64 %0, {%1, %1};" : "=l"(h2[2]) : "r"(__float_as_uint(ha.z)));
            asm("mov.b64 %0, {%1, %1};" : "=l"(h2[3]) : "r"(__float_as_uint(ha.w)));
            asm("mov.b64 %0, {%1, %1};" : "=l"(h2[4]) : "r"(__float_as_uint(hb.x)));
            asm("mov.b64 %0, {%1, %1};" : "=l"(h2[5]) : "r"(__float_as_uint(hb.y)));
            asm("mov.b64 %0, {%1, %1};" : "=l"(h2[6]) : "r"(__float_as_uint(hb.z)));
            asm("mov.b64 %0, {%1, %1};" : "=l"(h2[7]) : "r"(__float_as_uint(hb.w)));

            // W: cols 8cg..+3 at unit cg, cols 8cg+4..+7 at unit 8+cg
            ulonglong2 w0 = *reinterpret_cast<const ulonglong2*>(
                &Wt[k * 64 + (cg << 2)]);
            ulonglong2 w1 = *reinterpret_cast<const ulonglong2*>(
                &Wt[k * 64 + ((8 + cg) << 2)]);
#pragma unroll
            for (int i = 0; i < 8; i++) {
                asm("fma.rn.f32x2 %0, %1, %2, %0;"
                    : "+l"(acc[i][0]) : "l"(h2[i]), "l"(w0.x));
                asm("fma.rn.f32x2 %0, %1, %2, %0;"
                    : "+l"(acc[i][1]) : "l"(h2[i]), "l"(w0.y));
                asm("fma.rn.f32x2 %0, %1, %2, %0;"
                    : "+l"(acc[i][2]) : "l"(h2[i]), "l"(w1.x));
                asm("fma.rn.f32x2 %0, %1, %2, %0;"
                    : "+l"(acc[i][3]) : "l"(h2[i]), "l"(w1.y));
            }
        }
    }

    // Store 8 rows x 8 cols (2 x 16B per row)
#pragma unroll
    for (int i = 0; i < 8; i++) {
        int row = row0 + i;
        if (row < N_NODES) {
            float* gp = &g_feat[(size_t)row * D + cg * 8];
            reinterpret_cast<ulonglong2*>(gp)[0] = make_ulonglong2(acc[i][0], acc[i][1]);
            reinterpret_cast<ulonglong2*>(gp)[1] = make_ulonglong2(acc[i][2], acc[i][3]);
        }
    }
}

// ---------------------------------------------------------------------------
// Kernel 2: per-edge scatter. 16 threads per edge, one float4 each.
// out[dst] += g[src] * e   via red.global.add.v4.f32.
// ---------------------------------------------------------------------------
__global__ void scatter_kernel(const float* __restrict__ e,
                               const int* __restrict__ src,
                               const int* __restrict__ dst,
                               float* __restrict__ out) {
    long long t = (long long)blockIdx.x * blockDim.x + threadIdx.x;
    int edge = (int)(t >> 4);
    if (edge >= N_EDGES) return;
    int quad = ((int)t & 15) * 4;

    int   s  = src[edge];
    int   d  = dst[edge];
    float ev = e[edge];

    const float4 gv =
        *reinterpret_cast<const float4*>(&g_feat[(size_t)s * D + quad]);

    float4 m = make_float4(gv.x * ev, gv.y * ev, gv.z * ev, gv.w * ev);

    float* p = &out[(size_t)d * D + quad];
    asm volatile("red.global.add.v4.f32 [%0], {%1, %2, %3, %4};"
                 :: "l"(p), "f"(m.x), "f"(m.y), "f"(m.z), "f"(m.w)
                 : "memory");
}

// ---------------------------------------------------------------------------
extern "C" void kernel_launch(void* const* d_in, const int* in_sizes, int n_in,
                              void* d_out, int out_size) {
    const float* h   = (const float*)d_in[0];
    const float* e   = (const float*)d_in[1];
    const int*   src = (const int*)d_in[2];
    const int*   dst = (const int*)d_in[3];
    const float* W   = (const float*)d_in[4];
    const float* b   = (const float*)d_in[5];
    float*       out = (float*)d_out;

    // 1) g = h @ W^T  +  out = broadcast(b)  (fused)
    int tblocks = (N_NODES + BLOCK_ROWS - 1) / BLOCK_ROWS;   // 391
    transform_kernel<<<tblocks, T_TPB>>>(h, W, b, out);

    // 2) out[dst] += g[src] * e
    {
        long long total = (long long)N_EDGES * 16;
        int blocks = (int)((total + 255) / 256);
        scatter_kernel<<<blocks, 256>>>(e, src, dst, out);
    }
}

// round 11
// speedup vs baseline: 1.6946x; 1.0688x over previous
#include <cuda_runtime.h>
#include <cstdint>

#define N_NODES 100000
#define N_EDGES 1250000
#define D 64
#define NB 391              // ceil(100000/256)

// transform tiling
#define T_TPB 256
#define BLOCK_ROWS 256
#define KT 16
#define HS 380

// Scratch
__device__ float g_feat[(size_t)N_NODES * D];   // h @ W^T (25.6 MB)
__device__ int   deg_cnt[N_NODES];              // degree, then placement cursor
__device__ int   offs[N_NODES + 1];             // CSR offsets
__device__ int   partials[512];                 // block partial sums (padded)
__device__ int2  edge_s[N_EDGES];               // sorted (src, bitcast e)

// ---------------------------------------------------------------------------
// CSR build
// ---------------------------------------------------------------------------
__global__ void zero_deg_kernel() {
    int i = blockIdx.x * 256 + threadIdx.x;
    if (i < N_NODES) deg_cnt[i] = 0;
    if (i < 512) partials[i] = 0;
}

__global__ void hist_kernel(const int* __restrict__ dst) {
    int e = blockIdx.x * 256 + threadIdx.x;
    if (e < N_EDGES) atomicAdd(&deg_cnt[dst[e]], 1);
}

__global__ void partial_kernel() {
    __shared__ int s[256];
    int i = blockIdx.x * 256 + threadIdx.x;
    s[threadIdx.x] = (i < N_NODES) ? deg_cnt[i] : 0;
    __syncthreads();
    for (int off = 128; off > 0; off >>= 1) {
        if (threadIdx.x < off) s[threadIdx.x] += s[threadIdx.x + off];
        __syncthreads();
    }
    if (threadIdx.x == 0) partials[blockIdx.x] = s[0];
}

__global__ void scan_partials_kernel() {
    __shared__ int s[512];
    int tid = threadIdx.x;
    int v = partials[tid];                 // padded to 512 with zeros
    s[tid] = v;
    __syncthreads();
    for (int off = 1; off < 512; off <<= 1) {
        int t = (tid >= off) ? s[tid - off] : 0;
        __syncthreads();
        s[tid] += t;
        __syncthreads();
    }
    partials[tid] = s[tid] - v;            // exclusive
}

__global__ void offsets_kernel() {
    __shared__ int s[256];
    int tid = threadIdx.x;
    int i = blockIdx.x * 256 + tid;
    int v = (i < N_NODES) ? deg_cnt[i] : 0;
    s[tid] = v;
    __syncthreads();
    for (int off = 1; off < 256; off <<= 1) {
        int t = (tid >= off) ? s[tid - off] : 0;
        __syncthreads();
        s[tid] += t;
        __syncthreads();
    }
    int ex = s[tid] - v + partials[blockIdx.x];
    if (i < N_NODES) {
        offs[i] = ex;
        deg_cnt[i] = ex;                   // placement cursor
    }
    if (blockIdx.x == 0 && tid == 0) offs[N_NODES] = N_EDGES;
}

__global__ void place_kernel(const float* __restrict__ e,
                             const int* __restrict__ src,
                             const int* __restrict__ dst) {
    int i = blockIdx.x * 256 + threadIdx.x;
    if (i >= N_EDGES) return;
    int d   = dst[i];
    int pos = atomicAdd(&deg_cnt[d], 1);
    edge_s[pos] = make_int2(src[i], __float_as_int(e[i]));
}

// ---------------------------------------------------------------------------
// g = h @ W^T  (register-tiled f32x2, conflict-free smem layouts)
// ---------------------------------------------------------------------------
__global__ __launch_bounds__(T_TPB, 2) void transform_kernel(
        const float* __restrict__ h, const float* __restrict__ W) {
    __shared__ float Wt[D * D];
    __shared__ float hT[KT * HS];

    const int tid = threadIdx.x;

    for (int i = tid; i < D * D; i += T_TPB) {
        int o = i >> 6, k = i & 63;
        int u = o >> 2, el = o & 3;
        int p = ((u & 1) << 3) | (u >> 1);
        Wt[k * 64 + p * 4 + el] = W[i];
    }

    const int warp = tid >> 5;
    const int lane = tid & 31;
    const int cg   = lane & 7;
    const int rg   = warp * 4 + (lane >> 3);
    const int row0 = blockIdx.x * BLOCK_ROWS + rg * 8;
    const int rbp  = rg * 12;

    unsigned long long acc[8][4];
#pragma unroll
    for (int i = 0; i < 8; i++)
#pragma unroll
        for (int p = 0; p < 4; p++) acc[i][p] = 0ULL;

    const int base_row = blockIdx.x * BLOCK_ROWS;

    for (int kp = 0; kp < D / KT; kp++) {
        __syncthreads();
#pragma unroll
        for (int it = 0; it < 4; it++) {
            int gi  = tid + it * T_TPB;
            int row = gi & 255;
            int c4  = gi >> 8;
            int grow = base_row + row;
            if (grow > N_NODES - 1) grow = N_NODES - 1;
            float4 hv = *reinterpret_cast<const float4*>(
                &h[(size_t)grow * D + kp * KT + c4 * 4]);
            int rp = row + (row >> 3) * 4;
            hT[(c4 * 4 + 0) * HS + rp] = hv.x;
            hT[(c4 * 4 + 1) * HS + rp] = hv.y;
            hT[(c4 * 4 + 2) * HS + rp] = hv.z;
            hT[(c4 * 4 + 3) * HS + rp] = hv.w;
        }
        __syncthreads();

#pragma unroll 4
        for (int kl = 0; kl < KT; kl++) {
            const int k = kp * KT + kl;
            float4 ha = *reinterpret_cast<const float4*>(&hT[kl * HS + rbp]);
            float4 hb = *reinterpret_cast<const float4*>(&hT[kl * HS + rbp + 4]);
            unsigned long long h2[8];
            asm("mov.b64 %0, {%1, %1};" : "=l"(h2[0]) : "r"(__float_as_uint(ha.x)));
            asm("mov.b64 %0, {%1, %1};" : "=l"(h2[1]) : "r"(__float_as_uint(ha.y)));
            asm("mov.b64 %0, {%1, %1};" : "=l"(h2[2]) : "r"(__float_as_uint(ha.z)));
            asm("mov.b64 %0, {%1, %1};" : "=l"(h2[3]) : "r"(__float_as_uint(ha.w)));
            asm("mov.b64 %0, {%1, %1};" : "=l"(h2[4]) : "r"(__float_as_uint(hb.x)));
            asm("mov.b64 %0, {%1, %1};" : "=l"(h2[5]) : "r"(__float_as_uint(hb.y)));
            asm("mov.b64 %0, {%1, %1};" : "=l"(h2[6]) : "r"(__float_as_uint(hb.z)));
            asm("mov.b64 %0, {%1, %1};" : "=l"(h2[7]) : "r"(__float_as_uint(hb.w)));

            ulonglong2 w0 = *reinterpret_cast<const ulonglong2*>(
                &Wt[k * 64 + (cg << 2)]);
            ulonglong2 w1 = *reinterpret_cast<const ulonglong2*>(
                &Wt[k * 64 + ((8 + cg) << 2)]);
#pragma unroll
            for (int i = 0; i < 8; i++) {
                asm("fma.rn.f32x2 %0, %1, %2, %0;"
                    : "+l"(acc[i][0]) : "l"(h2[i]), "l"(w0.x));
                asm("fma.rn.f32x2 %0, %1, %2, %0;"
                    : "+l"(acc[i][1]) : "l"(h2[i]), "l"(w0.y));
                asm("fma.rn.f32x2 %0, %1, %2, %0;"
                    : "+l"(acc[i][2]) : "l"(h2[i]), "l"(w1.x));
                asm("fma.rn.f32x2 %0, %1, %2, %0;"
                    : "+l"(acc[i][3]) : "l"(h2[i]), "l"(w1.y));
            }
        }
    }

#pragma unroll
    for (int i = 0; i < 8; i++) {
        int row = row0 + i;
        if (row < N_NODES) {
            float* gp = &g_feat[(size_t)row * D + cg * 8];
            reinterpret_cast<ulonglong2*>(gp)[0] = make_ulonglong2(acc[i][0], acc[i][1]);
            reinterpret_cast<ulonglong2*>(gp)[1] = make_ulonglong2(acc[i][2], acc[i][3]);
        }
    }
}

// ---------------------------------------------------------------------------
// Aggregate: out[n] = b + sum_{edges->n} g[src]*e.  16 threads/node, plain ST.
// ---------------------------------------------------------------------------
__global__ __launch_bounds__(256) void aggregate_kernel(
        const float* __restrict__ bias, float* __restrict__ out) {
    int t = blockIdx.x * 256 + threadIdx.x;       // grid exactly N_NODES*16
    int node = t >> 4;
    int q    = (t & 15) * 4;

    float4 acc = __ldg(reinterpret_cast<const float4*>(&bias[q]));

    int i   = offs[node];
    int end = offs[node + 1];

    for (; i + 2 <= end; i += 2) {
        int2 p0 = edge_s[i];
        int2 p1 = edge_s[i + 1];
        const float4 g0 = *reinterpret_cast<const float4*>(
            &g_feat[(size_t)p0.x * D + q]);
        const float4 g1 = *reinterpret_cast<const float4*>(
            &g_feat[(size_t)p1.x * D + q]);
        float e0 = __int_as_float(p0.y), e1 = __int_as_float(p1.y);
        acc.x = fmaf(g0.x, e0, acc.x); acc.y = fmaf(g0.y, e0, acc.y);
        acc.z = fmaf(g0.z, e0, acc.z); acc.w = fmaf(g0.w, e0, acc.w);
        acc.x = fmaf(g1.x, e1, acc.x); acc.y = fmaf(g1.y, e1, acc.y);
        acc.z = fmaf(g1.z, e1, acc.z); acc.w = fmaf(g1.w, e1, acc.w);
    }
    if (i < end) {
        int2 p0 = edge_s[i];
        const float4 g0 = *reinterpret_cast<const float4*>(
            &g_feat[(size_t)p0.x * D + q]);
        float e0 = __int_as_float(p0.y);
        acc.x = fmaf(g0.x, e0, acc.x); acc.y = fmaf(g0.y, e0, acc.y);
        acc.z = fmaf(g0.z, e0, acc.z); acc.w = fmaf(g0.w, e0, acc.w);
    }

    *reinterpret_cast<float4*>(&out[(size_t)node * D + q]) = acc;
}

// ---------------------------------------------------------------------------
extern "C" void kernel_launch(void* const* d_in, const int* in_sizes, int n_in,
                              void* d_out, int out_size) {
    const float* h   = (const float*)d_in[0];
    const float* e   = (const float*)d_in[1];
    const int*   src = (const int*)d_in[2];
    const int*   dst = (const int*)d_in[3];
    const float* W   = (const float*)d_in[4];
    const float* b   = (const float*)d_in[5];
    float*       out = (float*)d_out;

    const int eb = (N_EDGES + 255) / 256;          // 4883

    // CSR build
    zero_deg_kernel<<<NB, 256>>>();
    hist_kernel<<<eb, 256>>>(dst);
    partial_kernel<<<NB, 256>>>();
    scan_partials_kernel<<<1, 512>>>();
    offsets_kernel<<<NB, 256>>>();
    place_kernel<<<eb, 256>>>(e, src, dst);

    // g = h @ W^T
    transform_kernel<<<NB, T_TPB>>>(h, W);

    // out = b + segment_sum(g[src] * e)
    aggregate_kernel<<<(N_NODES * 16) / 256, 256>>>(b, out);
}

// round 12
// speedup vs baseline: 1.8907x; 1.1158x over previous
#include <cuda_runtime.h>
#include <cstdint>

#define N_NODES 100000
#define N_EDGES 1250000
#define D 64
#define NB 391              // ceil(100000/256)

// transform tiling
#define T_TPB 256
#define BLOCK_ROWS 256
#define KT 16
#define HS 380

// Scratch
__device__ float g_feat[(size_t)N_NODES * D];   // h @ W^T (25.6 MB)
__device__ int   deg_cnt[N_NODES];              // degree, then placement cursor
__device__ int   offs[N_NODES + 1];             // CSR offsets
__device__ int   partials[512];                 // block partial sums (padded)
__device__ int2  edge_s[N_EDGES];               // binned (src, bitcast e)

// Side stream + fork/join events, created once before any harness checkpoint.
static cudaStream_t g_side = nullptr;
static cudaEvent_t  g_fork = nullptr, g_join = nullptr;
namespace {
struct StreamInit {
    StreamInit() {
        cudaStreamCreateWithFlags(&g_side, cudaStreamNonBlocking);
        cudaEventCreateWithFlags(&g_fork, cudaEventDisableTiming);
        cudaEventCreateWithFlags(&g_join, cudaEventDisableTiming);
    }
};
StreamInit g_stream_init;
}

// ---------------------------------------------------------------------------
// CSR build (side stream)
// ---------------------------------------------------------------------------
__global__ void zero_deg_kernel() {
    int i = blockIdx.x * 256 + threadIdx.x;
    if (i < N_NODES) deg_cnt[i] = 0;
    if (i < 512) partials[i] = 0;
}

__global__ void hist_kernel(const int* __restrict__ dst) {
    int e = blockIdx.x * 256 + threadIdx.x;
    if (e < N_EDGES) atomicAdd(&deg_cnt[dst[e]], 1);
}

__global__ void partial_kernel() {
    __shared__ int s[256];
    int i = blockIdx.x * 256 + threadIdx.x;
    s[threadIdx.x] = (i < N_NODES) ? deg_cnt[i] : 0;
    __syncthreads();
    for (int off = 128; off > 0; off >>= 1) {
        if (threadIdx.x < off) s[threadIdx.x] += s[threadIdx.x + off];
        __syncthreads();
    }
    if (threadIdx.x == 0) partials[blockIdx.x] = s[0];
}

__global__ void scan_partials_kernel() {
    __shared__ int s[512];
    int tid = threadIdx.x;
    int v = partials[tid];                 // padded to 512 with zeros
    s[tid] = v;
    __syncthreads();
    for (int off = 1; off < 512; off <<= 1) {
        int t = (tid >= off) ? s[tid - off] : 0;
        __syncthreads();
        s[tid] += t;
        __syncthreads();
    }
    partials[tid] = s[tid] - v;            // exclusive
}

__global__ void offsets_kernel() {
    __shared__ int s[256];
    int tid = threadIdx.x;
    int i = blockIdx.x * 256 + tid;
    int v = (i < N_NODES) ? deg_cnt[i] : 0;
    s[tid] = v;
    __syncthreads();
    for (int off = 1; off < 256; off <<= 1) {
        int t = (tid >= off) ? s[tid - off] : 0;
        __syncthreads();
        s[tid] += t;
        __syncthreads();
    }
    int ex = s[tid] - v + partials[blockIdx.x];
    if (i < N_NODES) {
        offs[i] = ex;
        deg_cnt[i] = ex;                   // placement cursor
    }
    if (blockIdx.x == 0 && tid == 0) offs[N_NODES] = N_EDGES;
}

__global__ void place_kernel(const float* __restrict__ e,
                             const int* __restrict__ src,
                             const int* __restrict__ dst) {
    int i = blockIdx.x * 256 + threadIdx.x;
    if (i >= N_EDGES) return;
    int d   = dst[i];
    int pos = atomicAdd(&deg_cnt[d], 1);
    edge_s[pos] = make_int2(src[i], __float_as_int(e[i]));
}

// ---------------------------------------------------------------------------
// g = h @ W^T  (register-tiled f32x2, conflict-free smem layouts)
// ---------------------------------------------------------------------------
__global__ __launch_bounds__(T_TPB, 2) void transform_kernel(
        const float* __restrict__ h, const float* __restrict__ W) {
    __shared__ float Wt[D * D];
    __shared__ float hT[KT * HS];

    const int tid = threadIdx.x;

    for (int i = tid; i < D * D; i += T_TPB) {
        int o = i >> 6, k = i & 63;
        int u = o >> 2, el = o & 3;
        int p = ((u & 1) << 3) | (u >> 1);
        Wt[k * 64 + p * 4 + el] = W[i];
    }

    const int warp = tid >> 5;
    const int lane = tid & 31;
    const int cg   = lane & 7;
    const int rg   = warp * 4 + (lane >> 3);
    const int row0 = blockIdx.x * BLOCK_ROWS + rg * 8;
    const int rbp  = rg * 12;

    unsigned long long acc[8][4];
#pragma unroll
    for (int i = 0; i < 8; i++)
#pragma unroll
        for (int p = 0; p < 4; p++) acc[i][p] = 0ULL;

    const int base_row = blockIdx.x * BLOCK_ROWS;

    for (int kp = 0; kp < D / KT; kp++) {
        __syncthreads();
#pragma unroll
        for (int it = 0; it < 4; it++) {
            int gi  = tid + it * T_TPB;
            int row = gi & 255;
            int c4  = gi >> 8;
            int grow = base_row + row;
            if (grow > N_NODES - 1) grow = N_NODES - 1;
            float4 hv = *reinterpret_cast<const float4*>(
                &h[(size_t)grow * D + kp * KT + c4 * 4]);
            int rp = row + (row >> 3) * 4;
            hT[(c4 * 4 + 0) * HS + rp] = hv.x;
            hT[(c4 * 4 + 1) * HS + rp] = hv.y;
            hT[(c4 * 4 + 2) * HS + rp] = hv.z;
            hT[(c4 * 4 + 3) * HS + rp] = hv.w;
        }
        __syncthreads();

#pragma unroll 4
        for (int kl = 0; kl < KT; kl++) {
            const int k = kp * KT + kl;
            float4 ha = *reinterpret_cast<const float4*>(&hT[kl * HS + rbp]);
            float4 hb = *reinterpret_cast<const float4*>(&hT[kl * HS + rbp + 4]);
            unsigned long long h2[8];
            asm("mov.b64 %0, {%1, %1};" : "=l"(h2[0]) : "r"(__float_as_uint(ha.x)));
            asm("mov.b64 %0, {%1, %1};" : "=l"(h2[1]) : "r"(__float_as_uint(ha.y)));
            asm("mov.b64 %0, {%1, %1};" : "=l"(h2[2]) : "r"(__float_as_uint(ha.z)));
            asm("mov.b64 %0, {%1, %1};" : "=l"(h2[3]) : "r"(__float_as_uint(ha.w)));
            asm("mov.b64 %0, {%1, %1};" : "=l"(h2[4]) : "r"(__float_as_uint(hb.x)));
            asm("mov.b64 %0, {%1, %1};" : "=l"(h2[5]) : "r"(__float_as_uint(hb.y)));
            asm("mov.b64 %0, {%1, %1};" : "=l"(h2[6]) : "r"(__float_as_uint(hb.z)));
            asm("mov.b64 %0, {%1, %1};" : "=l"(h2[7]) : "r"(__float_as_uint(hb.w)));

            ulonglong2 w0 = *reinterpret_cast<const ulonglong2*>(
                &Wt[k * 64 + (cg << 2)]);
            ulonglong2 w1 = *reinterpret_cast<const ulonglong2*>(
                &Wt[k * 64 + ((8 + cg) << 2)]);
#pragma unroll
            for (int i = 0; i < 8; i++) {
                asm("fma.rn.f32x2 %0, %1, %2, %0;"
                    : "+l"(acc[i][0]) : "l"(h2[i]), "l"(w0.x));
                asm("fma.rn.f32x2 %0, %1, %2, %0;"
                    : "+l"(acc[i][1]) : "l"(h2[i]), "l"(w0.y));
                asm("fma.rn.f32x2 %0, %1, %2, %0;"
                    : "+l"(acc[i][2]) : "l"(h2[i]), "l"(w1.x));
                asm("fma.rn.f32x2 %0, %1, %2, %0;"
                    : "+l"(acc[i][3]) : "l"(h2[i]), "l"(w1.y));
            }
        }
    }

#pragma unroll
    for (int i = 0; i < 8; i++) {
        int row = row0 + i;
        if (row < N_NODES) {
            float* gp = &g_feat[(size_t)row * D + cg * 8];
            reinterpret_cast<ulonglong2*>(gp)[0] = make_ulonglong2(acc[i][0], acc[i][1]);
            reinterpret_cast<ulonglong2*>(gp)[1] = make_ulonglong2(acc[i][2], acc[i][3]);
        }
    }
}

// ---------------------------------------------------------------------------
// Aggregate: out[n] = b + sum_{edges->n} g[src]*e.  16 threads/node, plain ST.
// ---------------------------------------------------------------------------
__global__ __launch_bounds__(256) void aggregate_kernel(
        const float* __restrict__ bias, float* __restrict__ out) {
    int t = blockIdx.x * 256 + threadIdx.x;       // grid exactly N_NODES*16
    int node = t >> 4;
    int q    = (t & 15) * 4;

    float4 acc = __ldg(reinterpret_cast<const float4*>(&bias[q]));

    int i   = offs[node];
    int end = offs[node + 1];

    for (; i + 2 <= end; i += 2) {
        int2 p0 = edge_s[i];
        int2 p1 = edge_s[i + 1];
        const float4 g0 = *reinterpret_cast<const float4*>(
            &g_feat[(size_t)p0.x * D + q]);
        const float4 g1 = *reinterpret_cast<const float4*>(
            &g_feat[(size_t)p1.x * D + q]);
        float e0 = __int_as_float(p0.y), e1 = __int_as_float(p1.y);
        acc.x = fmaf(g0.x, e0, acc.x); acc.y = fmaf(g0.y, e0, acc.y);
        acc.z = fmaf(g0.z, e0, acc.z); acc.w = fmaf(g0.w, e0, acc.w);
        acc.x = fmaf(g1.x, e1, acc.x); acc.y = fmaf(g1.y, e1, acc.y);
        acc.z = fmaf(g1.z, e1, acc.z); acc.w = fmaf(g1.w, e1, acc.w);
    }
    if (i < end) {
        int2 p0 = edge_s[i];
        const float4 g0 = *reinterpret_cast<const float4*>(
            &g_feat[(size_t)p0.x * D + q]);
        float e0 = __int_as_float(p0.y);
        acc.x = fmaf(g0.x, e0, acc.x); acc.y = fmaf(g0.y, e0, acc.y);
        acc.z = fmaf(g0.z, e0, acc.z); acc.w = fmaf(g0.w, e0, acc.w);
    }

    *reinterpret_cast<float4*>(&out[(size_t)node * D + q]) = acc;
}

// ---------------------------------------------------------------------------
extern "C" void kernel_launch(void* const* d_in, const int* in_sizes, int n_in,
                              void* d_out, int out_size) {
    const float* h   = (const float*)d_in[0];
    const float* e   = (const float*)d_in[1];
    const int*   src = (const int*)d_in[2];
    const int*   dst = (const int*)d_in[3];
    const float* W   = (const float*)d_in[4];
    const float* b   = (const float*)d_in[5];
    float*       out = (float*)d_out;

    const int eb = (N_EDGES + 255) / 256;          // 4883

    // Fork: CSR build on side stream, transform on main stream (independent).
    cudaEventRecord(g_fork, 0);
    cudaStreamWaitEvent(g_side, g_fork, 0);

    zero_deg_kernel<<<NB, 256, 0, g_side>>>();
    hist_kernel<<<eb, 256, 0, g_side>>>(dst);
    partial_kernel<<<NB, 256, 0, g_side>>>();
    scan_partials_kernel<<<1, 512, 0, g_side>>>();
    offsets_kernel<<<NB, 256, 0, g_side>>>();
    place_kernel<<<eb, 256, 0, g_side>>>(e, src, dst);
    cudaEventRecord(g_join, g_side);

    // g = h @ W^T  (main stream, overlaps with CSR build)
    transform_kernel<<<NB, T_TPB>>>(h, W);

    // Join, then aggregate: out = b + segment_sum(g[src] * e)
    cudaStreamWaitEvent(0, g_join, 0);
    aggregate_kernel<<<(N_NODES * 16) / 256, 256>>>(b, out);
}